// round 8
// baseline (speedup 1.0000x reference)
#include <cuda_runtime.h>
#include <cuda_bf16.h>
#include <cuda_fp16.h>
#include <cstdint>
#include <math.h>

#define NN 8192
#define FD 256
#define ALPHA_S 0.2f

// ---------------- device global scratch ----------------
__device__ __nv_bfloat16 g_hhi[NN * FD];
__device__ __nv_bfloat16 g_hlo[NN * FD];
__device__ __nv_bfloat16 g_WThi[FD * FD];
__device__ __nv_bfloat16 g_WTlo[FD * FD];
__device__ __half g_WhThi[FD * NN];   // Wh^T [n][k] fp16 hi/lo
__device__ __half g_WhTlo[FD * NN];
__device__ float g_f1[NN];
__device__ float g_f2[NN];
__device__ unsigned int g_f2max_bits;

__device__ __forceinline__ unsigned int fkey(float f) {
    unsigned int b = __float_as_uint(f);
    return (b & 0x80000000u) ? ~b : (b | 0x80000000u);
}
__device__ __forceinline__ float fdec(unsigned int k) {
    unsigned int b = (k & 0x80000000u) ? (k & 0x7fffffffu) : ~k;
    return __uint_as_float(b);
}

// ---------------- PTX helpers ----------------
__device__ __forceinline__ uint32_t smem_u32(const void* p) {
    uint32_t a;
    asm("{ .reg .u64 t; cvta.to.shared.u64 t, %1; cvt.u32.u64 %0, t; }"
        : "=r"(a) : "l"(p));
    return a;
}
__device__ __forceinline__ void cp_async16(uint32_t dst, const void* src) {
    asm volatile("cp.async.cg.shared.global [%0], [%1], 16;"
                 :: "r"(dst), "l"(src) : "memory");
}
__device__ __forceinline__ void cp_commit() {
    asm volatile("cp.async.commit_group;" ::: "memory");
}
template<int N>
__device__ __forceinline__ void cp_wait() {
    asm volatile("cp.async.wait_group %0;" :: "n"(N) : "memory");
}
__device__ __forceinline__ void ldm_x4(uint32_t addr, uint32_t& r0, uint32_t& r1,
                                       uint32_t& r2, uint32_t& r3) {
    asm volatile("ldmatrix.sync.aligned.m8n8.x4.shared.b16 {%0,%1,%2,%3}, [%4];"
                 : "=r"(r0), "=r"(r1), "=r"(r2), "=r"(r3) : "r"(addr));
}
__device__ __forceinline__ void mma_bf16(float* c, const uint32_t* a, const uint32_t* b) {
    asm volatile(
        "mma.sync.aligned.m16n8k16.row.col.f32.bf16.bf16.f32 "
        "{%0,%1,%2,%3}, {%4,%5,%6,%7}, {%8,%9}, {%0,%1,%2,%3};"
        : "+f"(c[0]), "+f"(c[1]), "+f"(c[2]), "+f"(c[3])
        : "r"(a[0]), "r"(a[1]), "r"(a[2]), "r"(a[3]), "r"(b[0]), "r"(b[1]));
}
__device__ __forceinline__ void mma_fp16(float* c, const uint32_t* a, const uint32_t* b) {
    asm volatile(
        "mma.sync.aligned.m16n8k16.row.col.f32.f16.f16.f32 "
        "{%0,%1,%2,%3}, {%4,%5,%6,%7}, {%8,%9}, {%0,%1,%2,%3};"
        : "+f"(c[0]), "+f"(c[1]), "+f"(c[2]), "+f"(c[3])
        : "r"(a[0]), "r"(a[1]), "r"(a[2]), "r"(a[3]), "r"(b[0]), "r"(b[1]));
}

// ======================= GEMM1: Wh = h @ W (bf16 3-pass) ====
static constexpr int ROWB    = 80;
static constexpr int TILE_B  = 128 * ROWB;
static constexpr int STAGE_B = 4 * TILE_B;
static constexpr int SMEM1_SZ = 2 * STAGE_B;      // 81920

template<int KCHUNKS>
__global__ void __launch_bounds__(256, 1) mma_gemm1(
    const __nv_bfloat16* __restrict__ Ahi, const __nv_bfloat16* __restrict__ Alo,
    const __nv_bfloat16* __restrict__ Bhi, const __nv_bfloat16* __restrict__ Blo,
    __half* __restrict__ ThiOut, __half* __restrict__ TloOut)
{
    constexpr int K = KCHUNKS * 32;
    extern __shared__ char smem[];
    const uint32_t sb = smem_u32(smem);

    const int tid  = threadIdx.x;
    const int warp = tid >> 5;
    const int lane = tid & 31;
    const int wm   = warp & 3;
    const int wn   = warp >> 2;
    const int row0 = blockIdx.x * 128;
    const int col0 = blockIdx.y * 128;

    const int a_row = lane & 15;
    const int a_kb  = (lane >> 4) * 16;
    const int b_row = ((lane >> 4) << 3) + (lane & 7);
    const int b_kb  = ((lane >> 3) & 1) * 16;
    const int lrow = tid >> 2;
    const int lch  = tid & 3;

    float acc[2][8][4];
    #pragma unroll
    for (int i = 0; i < 2; i++)
        #pragma unroll
        for (int j = 0; j < 8; j++)
            #pragma unroll
            for (int q = 0; q < 4; q++) acc[i][j][q] = 0.0f;

    auto load_stage = [&](int s, int kc) {
        const uint32_t base = sb + s * STAGE_B;
        const int k0 = kc * 32;
        #pragma unroll
        for (int it = 0; it < 2; it++) {
            int r = lrow + it * 64;
            uint32_t doff = r * ROWB + lch * 16;
            size_t ga = (size_t)(row0 + r) * K + k0 + lch * 8;
            size_t gb = (size_t)(col0 + r) * K + k0 + lch * 8;
            cp_async16(base + 0 * TILE_B + doff, Ahi + ga);
            cp_async16(base + 1 * TILE_B + doff, Alo + ga);
            cp_async16(base + 2 * TILE_B + doff, Bhi + gb);
            cp_async16(base + 3 * TILE_B + doff, Blo + gb);
        }
        cp_commit();
    };

    load_stage(0, 0);

    for (int c = 0; c < KCHUNKS; c++) {
        const int s = c & 1;
        if (c + 1 < KCHUNKS) { load_stage(s ^ 1, c + 1); cp_wait<1>(); }
        else                 { cp_wait<0>(); }
        __syncthreads();

        const uint32_t base = sb + s * STAGE_B;
        #pragma unroll
        for (int ks = 0; ks < 2; ks++) {
            const int kb = ks * 32;
            uint32_t ah[2][4], al[2][4], bh[16], bl[16];
            #pragma unroll
            for (int mt = 0; mt < 2; mt++) {
                uint32_t ra = (wm * 32 + mt * 16 + a_row) * ROWB + kb + a_kb;
                ldm_x4(base + 0 * TILE_B + ra, ah[mt][0], ah[mt][1], ah[mt][2], ah[mt][3]);
                ldm_x4(base + 1 * TILE_B + ra, al[mt][0], al[mt][1], al[mt][2], al[mt][3]);
            }
            #pragma unroll
            for (int nb = 0; nb < 4; nb++) {
                uint32_t rb = (wn * 64 + nb * 16 + b_row) * ROWB + kb + b_kb;
                ldm_x4(base + 2 * TILE_B + rb, bh[4*nb], bh[4*nb+1], bh[4*nb+2], bh[4*nb+3]);
                ldm_x4(base + 3 * TILE_B + rb, bl[4*nb], bl[4*nb+1], bl[4*nb+2], bl[4*nb+3]);
            }
            #pragma unroll
            for (int mt = 0; mt < 2; mt++)
                #pragma unroll
                for (int nt = 0; nt < 8; nt++) {
                    mma_bf16(acc[mt][nt], ah[mt], bh + 2*nt);
                    mma_bf16(acc[mt][nt], ah[mt], bl + 2*nt);
                    mma_bf16(acc[mt][nt], al[mt], bh + 2*nt);
                }
        }
        __syncthreads();
    }

    // stage C^T fp16 hi/lo through smem, then coalesced store to [n][m]
    constexpr int TST = 272;
    __half* shT = (__half*)smem;
    __half* slT = (__half*)(smem + 128 * TST);
    #pragma unroll
    for (int mt = 0; mt < 2; mt++) {
        #pragma unroll
        for (int nt = 0; nt < 8; nt++) {
            int ml = wm * 32 + mt * 16 + (lane >> 2);
            int nl = wn * 64 + nt * 8 + (lane & 3) * 2;
            #pragma unroll
            for (int q = 0; q < 4; q++) {
                int m = ml + (q >> 1) * 8;
                int n = nl + (q & 1);
                float v = acc[mt][nt][q];
                __half hb = __float2half_rn(v);
                __half lb = __float2half_rn(v - __half2float(hb));
                shT[n * 136 + m] = hb;
                slT[n * 136 + m] = lb;
            }
        }
    }
    __syncthreads();
    #pragma unroll
    for (int it = 0; it < 8; it++) {
        int idx = tid + it * 256;
        int n = idx >> 4, cm = idx & 15;
        uint4 vh = *(uint4*)(smem + n * TST + cm * 16);
        uint4 vl = *(uint4*)(smem + 128 * TST + n * TST + cm * 16);
        size_t g = (size_t)(col0 + n) * NN + row0 + cm * 8;
        *(uint4*)(ThiOut + g) = vh;
        *(uint4*)(TloOut + g) = vl;
    }
}

// ======================= fused softmax + P@Wh GEMM ========================
// 256 threads (8 warps), tile M=32 x N=256, K=8192 in 256 chunks of 32.
// TWO CTAs per SM (83KB smem, <=128 regs) so bubbles overlap.
// A = p (fp16), B = WhT fp16 single pass; one sync per chunk; triple-buffered.
static constexpr int FB_STG    = 256 * 80;                   // 20480
static constexpr int F_OFF_ADJ = 3 * FB_STG;                 // 61440
static constexpr int F_ADJ_STG = 32 * 144;                   // 4608
static constexpr int F_OFF_A   = F_OFF_ADJ + 3 * F_ADJ_STG;  // 75264
static constexpr int F_A_STG   = 32 * 80;                    // 2560
static constexpr int F_OFF_RS  = F_OFF_A + 3 * F_A_STG;      // 82944
static constexpr int SMEM2_SZ  = F_OFF_RS + 128;             // 83072

__global__ void __launch_bounds__(256, 2) fused_gemm2(
    const int* __restrict__ adj, float* __restrict__ out)
{
    extern __shared__ char smem[];
    const uint32_t sb = smem_u32(smem);
    const int tid  = threadIdx.x;
    const int warp = tid >> 5;           // 8 warps: cols warp*32
    const int lane = tid & 31;
    const int row0 = blockIdx.x * 32;

    const int a_row = lane & 15;
    const int a_kb  = (lane >> 4) * 16;
    const int b_row = ((lane >> 4) << 3) + (lane & 7);
    const int b_kb  = ((lane >> 3) & 1) * 16;

    // p-compute mapping: thread owns row rA=(tid>>3), cols [(tid&7)*4, +4)
    const int rA = tid >> 3;             // 0..31
    const int ch = tid & 7;

    auto load_B = [&](int slot, int c) {
        const uint32_t bb = sb + slot * FB_STG;
        const int k0 = c * 32;
        #pragma unroll
        for (int it = 0; it < 4; it++) {
            int idx = tid + it * 256;    // 0..1023
            int n = idx >> 2, c4 = idx & 3;
            cp_async16(bb + n * 80 + c4 * 16,
                       g_WhThi + (size_t)n * NN + k0 + c4 * 8);
        }
    };
    auto load_adj = [&](int slot, int c) {
        const uint32_t ab = sb + F_OFF_ADJ + slot * F_ADJ_STG;
        cp_async16(ab + rA * 144 + ch * 16,
                   adj + (size_t)(row0 + rA) * NN + c * 32 + ch * 4);
    };

    // row constants; per-row shifts cancel in softmax
    const float f2max = fdec(g_f2max_bits);
    const float f1A = g_f1[row0 + rA];
    float tA = f1A + f2max;  const float CrA = tA > 0.f ? tA : ALPHA_S * tA;
    float psumA = 0.f;

    auto compute_p = [&](int c, int aslot, int abuf) {
        const char* ab = smem + F_OFF_ADJ + aslot * F_ADJ_STG + rA * 144 + ch * 16;
        int4 av = *(const int4*)ab;
        float4 f2v = *(const float4*)(g_f2 + c * 32 + ch * 4);
        float a0 = f1A + f2v.x; a0 = a0 > 0.f ? a0 : ALPHA_S * a0;
        float a1 = f1A + f2v.y; a1 = a1 > 0.f ? a1 : ALPHA_S * a1;
        float a2 = f1A + f2v.z; a2 = a2 > 0.f ? a2 : ALPHA_S * a2;
        float a3 = f1A + f2v.w; a3 = a3 > 0.f ? a3 : ALPHA_S * a3;
        float p0 = av.x > 0 ? __expf(a0 - CrA) : 0.f;
        float p1 = av.y > 0 ? __expf(a1 - CrA) : 0.f;
        float p2 = av.z > 0 ? __expf(a2 - CrA) : 0.f;
        float p3 = av.w > 0 ? __expf(a3 - CrA) : 0.f;
        psumA += (p0 + p1) + (p2 + p3);
        __half2 h01 = __floats2half2_rn(p0, p1);
        __half2 h23 = __floats2half2_rn(p2, p3);
        uint2 w; w.x = *(uint32_t*)&h01; w.y = *(uint32_t*)&h23;
        *(uint2*)(smem + F_OFF_A + abuf * F_A_STG + rA * 80 + ch * 8) = w;
    };

    float acc[2][4][4];
    #pragma unroll
    for (int i = 0; i < 2; i++)
        #pragma unroll
        for (int j = 0; j < 4; j++)
            #pragma unroll
            for (int q = 0; q < 4; q++) acc[i][j][q] = 0.0f;

    // prologue: groups G1{adj0}, G2{B0,adj1}, G3{B1,adj2}
    load_adj(0, 0);               cp_commit();
    load_B(0, 0); load_adj(1, 1); cp_commit();
    load_B(1, 1); load_adj(2, 2); cp_commit();
    cp_wait<2>();                        // adj0 ready
    compute_p(0, 0, 0);                  // p[0] -> A[0]

    int bR = 0, bW = 2, aR3 = 1, aW = 0, aBufW = 1;
    for (int c = 0; c < 256; c++) {
        // outstanding groups ensure B(c), adj(c+1) done after wait<1>
        cp_wait<1>();

        if (c + 1 < 256) compute_p(c + 1, aR3, aBufW);
        __syncthreads();

        if (c + 2 < 256) load_B(bW, c + 2);
        if (c + 3 < 256) load_adj(aW, c + 3);
        cp_commit();

        // ---- MMA on chunk c ----
        const uint32_t bbase = sb + bR * FB_STG;
        const uint32_t abase = sb + F_OFF_A + (aBufW == 0 ? 2 : aBufW - 1) * F_A_STG;
        #pragma unroll
        for (int ks = 0; ks < 2; ks++) {
            const int kb = ks * 32;
            uint32_t af[2][4], bh[8];
            #pragma unroll
            for (int mt = 0; mt < 2; mt++) {
                uint32_t ra = abase + (mt * 16 + a_row) * 80 + kb + a_kb;
                ldm_x4(ra, af[mt][0], af[mt][1], af[mt][2], af[mt][3]);
            }
            #pragma unroll
            for (int nb = 0; nb < 2; nb++) {
                uint32_t rb = bbase + (warp * 32 + nb * 16 + b_row) * 80 + kb + b_kb;
                ldm_x4(rb, bh[4*nb], bh[4*nb+1], bh[4*nb+2], bh[4*nb+3]);
            }
            #pragma unroll
            for (int mt = 0; mt < 2; mt++)
                #pragma unroll
                for (int nt = 0; nt < 4; nt++)
                    mma_fp16(acc[mt][nt], af[mt], bh + 2*nt);
        }

        bR = bR == 2 ? 0 : bR + 1;    bW = bW == 2 ? 0 : bW + 1;
        aR3 = aR3 == 2 ? 0 : aR3 + 1; aW = aW == 2 ? 0 : aW + 1;
        aBufW = aBufW == 2 ? 0 : aBufW + 1;
    }

    // ---- rowsum reduce (8 threads per row, consecutive lanes) ----
    psumA += __shfl_xor_sync(0xffffffffu, psumA, 1);
    psumA += __shfl_xor_sync(0xffffffffu, psumA, 2);
    psumA += __shfl_xor_sync(0xffffffffu, psumA, 4);
    __syncthreads();
    if (ch == 0) *(float*)(smem + F_OFF_RS + rA * 4) = psumA;
    __syncthreads();
    const float* rs = (const float*)(smem + F_OFF_RS);

    // ---- epilogue: out = elu(acc / rowsum) ----
    #pragma unroll
    for (int mt = 0; mt < 2; mt++) {
        int rAl = mt * 16 + (lane >> 2);
        int rBl = rAl + 8;
        float invA = 1.0f / rs[rAl];
        float invB = 1.0f / rs[rBl];
        #pragma unroll
        for (int nt = 0; nt < 4; nt++) {
            int cc = warp * 32 + nt * 8 + (lane & 3) * 2;
            float v0 = acc[mt][nt][0] * invA;
            float v1 = acc[mt][nt][1] * invA;
            float v2 = acc[mt][nt][2] * invB;
            float v3 = acc[mt][nt][3] * invB;
            float2 oA = { v0 > 0.f ? v0 : expm1f(v0), v1 > 0.f ? v1 : expm1f(v1) };
            float2 oB = { v2 > 0.f ? v2 : expm1f(v2), v3 > 0.f ? v3 : expm1f(v3) };
            *(float2*)(out + (size_t)(row0 + rAl) * FD + cc) = oA;
            *(float2*)(out + (size_t)(row0 + rBl) * FD + cc) = oB;
        }
    }
}

// ---------------- input conversion ----------------
__global__ void convert_kernel(const float* __restrict__ h, const float* __restrict__ W)
{
    if (blockIdx.x == 0 && threadIdx.x == 0) g_f2max_bits = 0u;
    int t = blockIdx.x * 256 + threadIdx.x;
    if (blockIdx.x < NN) {
        float v = h[t];
        __nv_bfloat16 hb = __float2bfloat16(v);
        g_hhi[t] = hb;
        g_hlo[t] = __float2bfloat16(v - __bfloat162float(hb));
    } else {
        int idx = t - NN * 256;
        int o = idx >> 8, i = idx & 255;
        float v = W[i * FD + o];
        __nv_bfloat16 hb = __float2bfloat16(v);
        g_WThi[idx] = hb;
        g_WTlo[idx] = __float2bfloat16(v - __bfloat162float(hb));
    }
}

// ---------------- f1/f2 from WhT splits + global f2 max ----------------
__global__ void f1f2_kernel(const float* __restrict__ a)
{
    __shared__ float red[256];
    int tid = threadIdx.x;
    int m = blockIdx.x * 256 + tid;
    float s1 = 0.0f, s2 = 0.0f;
    #pragma unroll 4
    for (int n = 0; n < FD; n++) {
        float v = __half2float(g_WhThi[(size_t)n * NN + m]) +
                  __half2float(g_WhTlo[(size_t)n * NN + m]);
        s1 = fmaf(v, __ldg(a + n),      s1);
        s2 = fmaf(v, __ldg(a + FD + n), s2);
    }
    g_f1[m] = s1;
    g_f2[m] = s2;

    red[tid] = s2; __syncthreads();
    #pragma unroll
    for (int s = 128; s > 0; s >>= 1) {
        if (tid < s) red[tid] = fmaxf(red[tid], red[tid + s]);
        __syncthreads();
    }
    if (tid == 0) atomicMax(&g_f2max_bits, fkey(red[0]));
}

// ---------------- launch ----------------
extern "C" void kernel_launch(void* const* d_in, const int* in_sizes, int n_in,
                              void* d_out, int out_size)
{
    const float* h   = (const float*)d_in[0];
    const int*   adj = (const int*)  d_in[1];
    const float* W   = (const float*)d_in[3];
    const float* a   = (const float*)d_in[4];
    float* out = (float*)d_out;

    __nv_bfloat16 *phhi, *phlo, *pWThi, *pWTlo;
    __half *pWhThi, *pWhTlo;
    cudaGetSymbolAddress((void**)&phhi,   g_hhi);
    cudaGetSymbolAddress((void**)&phlo,   g_hlo);
    cudaGetSymbolAddress((void**)&pWThi,  g_WThi);
    cudaGetSymbolAddress((void**)&pWTlo,  g_WTlo);
    cudaGetSymbolAddress((void**)&pWhThi, g_WhThi);
    cudaGetSymbolAddress((void**)&pWhTlo, g_WhTlo);

    cudaFuncSetAttribute(mma_gemm1<8>, cudaFuncAttributeMaxDynamicSharedMemorySize, SMEM1_SZ);
    cudaFuncSetAttribute(fused_gemm2,  cudaFuncAttributeMaxDynamicSharedMemorySize, SMEM2_SZ);

    // 1) bf16 hi/lo splits of h and W^T (+ f2max init)
    convert_kernel<<<NN + FD, 256>>>(h, W);

    // 2) Wh = h@W (bf16 3-pass); epilogue writes WhT fp16 hi/lo
    {
        dim3 grid(NN / 128, FD / 128);
        mma_gemm1<8><<<grid, 256, SMEM1_SZ>>>(
            phhi, phlo, pWThi, pWTlo, pWhThi, pWhTlo);
    }

    // 3) f1/f2 (full precision hi+lo) + global f2 max
    f1f2_kernel<<<NN / 256, 256>>>(a);

    // 4) fused masked-softmax + (P @ Wh)/rowsum + ELU (2 CTAs/SM)
    fused_gemm2<<<NN / 32, 256, SMEM2_SZ>>>(adj, out);
}

// round 9
// speedup vs baseline: 1.0223x; 1.0223x over previous
#include <cuda_runtime.h>
#include <cuda_bf16.h>
#include <cuda_fp16.h>
#include <cstdint>
#include <math.h>

#define NN 8192
#define FD 256
#define ALPHA_S 0.2f

// ---------------- device global scratch ----------------
__device__ __nv_bfloat16 g_hhi[NN * FD];
__device__ __nv_bfloat16 g_hlo[NN * FD];
__device__ __nv_bfloat16 g_WThi[FD * FD];
__device__ __nv_bfloat16 g_WTlo[FD * FD];
__device__ __half g_WhThi[FD * NN];   // Wh^T [n][k] fp16 hi/lo
__device__ __half g_WhTlo[FD * NN];
__device__ float g_f1[NN];
__device__ float g_f2[NN];
__device__ unsigned int g_f2max_bits;

__device__ __forceinline__ unsigned int fkey(float f) {
    unsigned int b = __float_as_uint(f);
    return (b & 0x80000000u) ? ~b : (b | 0x80000000u);
}
__device__ __forceinline__ float fdec(unsigned int k) {
    unsigned int b = (k & 0x80000000u) ? (k & 0x7fffffffu) : ~k;
    return __uint_as_float(b);
}

// ---------------- PTX helpers ----------------
__device__ __forceinline__ uint32_t smem_u32(const void* p) {
    uint32_t a;
    asm("{ .reg .u64 t; cvta.to.shared.u64 t, %1; cvt.u32.u64 %0, t; }"
        : "=r"(a) : "l"(p));
    return a;
}
__device__ __forceinline__ void cp_async16(uint32_t dst, const void* src) {
    asm volatile("cp.async.cg.shared.global [%0], [%1], 16;"
                 :: "r"(dst), "l"(src) : "memory");
}
__device__ __forceinline__ void cp_commit() {
    asm volatile("cp.async.commit_group;" ::: "memory");
}
template<int N>
__device__ __forceinline__ void cp_wait() {
    asm volatile("cp.async.wait_group %0;" :: "n"(N) : "memory");
}
__device__ __forceinline__ void ldm_x4(uint32_t addr, uint32_t& r0, uint32_t& r1,
                                       uint32_t& r2, uint32_t& r3) {
    asm volatile("ldmatrix.sync.aligned.m8n8.x4.shared.b16 {%0,%1,%2,%3}, [%4];"
                 : "=r"(r0), "=r"(r1), "=r"(r2), "=r"(r3) : "r"(addr));
}
__device__ __forceinline__ void mma_bf16(float* c, const uint32_t* a, const uint32_t* b) {
    asm volatile(
        "mma.sync.aligned.m16n8k16.row.col.f32.bf16.bf16.f32 "
        "{%0,%1,%2,%3}, {%4,%5,%6,%7}, {%8,%9}, {%0,%1,%2,%3};"
        : "+f"(c[0]), "+f"(c[1]), "+f"(c[2]), "+f"(c[3])
        : "r"(a[0]), "r"(a[1]), "r"(a[2]), "r"(a[3]), "r"(b[0]), "r"(b[1]));
}
__device__ __forceinline__ void mma_fp16(float* c, const uint32_t* a, const uint32_t* b) {
    asm volatile(
        "mma.sync.aligned.m16n8k16.row.col.f32.f16.f16.f32 "
        "{%0,%1,%2,%3}, {%4,%5,%6,%7}, {%8,%9}, {%0,%1,%2,%3};"
        : "+f"(c[0]), "+f"(c[1]), "+f"(c[2]), "+f"(c[3])
        : "r"(a[0]), "r"(a[1]), "r"(a[2]), "r"(a[3]), "r"(b[0]), "r"(b[1]));
}
__device__ __forceinline__ void bar_sync640(int id) {
    asm volatile("bar.sync %0, 640;" :: "r"(id) : "memory");
}
__device__ __forceinline__ void bar_arrive640(int id) {
    asm volatile("bar.arrive %0, 640;" :: "r"(id) : "memory");
}

// ======================= GEMM1: Wh = h @ W (bf16 3-pass) ====
static constexpr int ROWB    = 80;
static constexpr int TILE_B  = 128 * ROWB;
static constexpr int STAGE_B = 4 * TILE_B;
static constexpr int SMEM1_SZ = 2 * STAGE_B;      // 81920

template<int KCHUNKS>
__global__ void __launch_bounds__(256, 1) mma_gemm1(
    const __nv_bfloat16* __restrict__ Ahi, const __nv_bfloat16* __restrict__ Alo,
    const __nv_bfloat16* __restrict__ Bhi, const __nv_bfloat16* __restrict__ Blo,
    __half* __restrict__ ThiOut, __half* __restrict__ TloOut)
{
    constexpr int K = KCHUNKS * 32;
    extern __shared__ char smem[];
    const uint32_t sb = smem_u32(smem);

    const int tid  = threadIdx.x;
    const int warp = tid >> 5;
    const int lane = tid & 31;
    const int wm   = warp & 3;
    const int wn   = warp >> 2;
    const int row0 = blockIdx.x * 128;
    const int col0 = blockIdx.y * 128;

    const int a_row = lane & 15;
    const int a_kb  = (lane >> 4) * 16;
    const int b_row = ((lane >> 4) << 3) + (lane & 7);
    const int b_kb  = ((lane >> 3) & 1) * 16;
    const int lrow = tid >> 2;
    const int lch  = tid & 3;

    float acc[2][8][4];
    #pragma unroll
    for (int i = 0; i < 2; i++)
        #pragma unroll
        for (int j = 0; j < 8; j++)
            #pragma unroll
            for (int q = 0; q < 4; q++) acc[i][j][q] = 0.0f;

    auto load_stage = [&](int s, int kc) {
        const uint32_t base = sb + s * STAGE_B;
        const int k0 = kc * 32;
        #pragma unroll
        for (int it = 0; it < 2; it++) {
            int r = lrow + it * 64;
            uint32_t doff = r * ROWB + lch * 16;
            size_t ga = (size_t)(row0 + r) * K + k0 + lch * 8;
            size_t gb = (size_t)(col0 + r) * K + k0 + lch * 8;
            cp_async16(base + 0 * TILE_B + doff, Ahi + ga);
            cp_async16(base + 1 * TILE_B + doff, Alo + ga);
            cp_async16(base + 2 * TILE_B + doff, Bhi + gb);
            cp_async16(base + 3 * TILE_B + doff, Blo + gb);
        }
        cp_commit();
    };

    load_stage(0, 0);

    for (int c = 0; c < KCHUNKS; c++) {
        const int s = c & 1;
        if (c + 1 < KCHUNKS) { load_stage(s ^ 1, c + 1); cp_wait<1>(); }
        else                 { cp_wait<0>(); }
        __syncthreads();

        const uint32_t base = sb + s * STAGE_B;
        #pragma unroll
        for (int ks = 0; ks < 2; ks++) {
            const int kb = ks * 32;
            uint32_t ah[2][4], al[2][4], bh[16], bl[16];
            #pragma unroll
            for (int mt = 0; mt < 2; mt++) {
                uint32_t ra = (wm * 32 + mt * 16 + a_row) * ROWB + kb + a_kb;
                ldm_x4(base + 0 * TILE_B + ra, ah[mt][0], ah[mt][1], ah[mt][2], ah[mt][3]);
                ldm_x4(base + 1 * TILE_B + ra, al[mt][0], al[mt][1], al[mt][2], al[mt][3]);
            }
            #pragma unroll
            for (int nb = 0; nb < 4; nb++) {
                uint32_t rb = (wn * 64 + nb * 16 + b_row) * ROWB + kb + b_kb;
                ldm_x4(base + 2 * TILE_B + rb, bh[4*nb], bh[4*nb+1], bh[4*nb+2], bh[4*nb+3]);
                ldm_x4(base + 3 * TILE_B + rb, bl[4*nb], bl[4*nb+1], bl[4*nb+2], bl[4*nb+3]);
            }
            #pragma unroll
            for (int mt = 0; mt < 2; mt++)
                #pragma unroll
                for (int nt = 0; nt < 8; nt++) {
                    mma_bf16(acc[mt][nt], ah[mt], bh + 2*nt);
                    mma_bf16(acc[mt][nt], ah[mt], bl + 2*nt);
                    mma_bf16(acc[mt][nt], al[mt], bh + 2*nt);
                }
        }
        __syncthreads();
    }

    // stage C^T fp16 hi/lo through smem, then coalesced store to [n][m]
    constexpr int TST = 272;
    __half* shT = (__half*)smem;
    __half* slT = (__half*)(smem + 128 * TST);
    #pragma unroll
    for (int mt = 0; mt < 2; mt++) {
        #pragma unroll
        for (int nt = 0; nt < 8; nt++) {
            int ml = wm * 32 + mt * 16 + (lane >> 2);
            int nl = wn * 64 + nt * 8 + (lane & 3) * 2;
            #pragma unroll
            for (int q = 0; q < 4; q++) {
                int m = ml + (q >> 1) * 8;
                int n = nl + (q & 1);
                float v = acc[mt][nt][q];
                __half hb = __float2half_rn(v);
                __half lb = __float2half_rn(v - __half2float(hb));
                shT[n * 136 + m] = hb;
                slT[n * 136 + m] = lb;
            }
        }
    }
    __syncthreads();
    #pragma unroll
    for (int it = 0; it < 8; it++) {
        int idx = tid + it * 256;
        int n = idx >> 4, cm = idx & 15;
        uint4 vh = *(uint4*)(smem + n * TST + cm * 16);
        uint4 vl = *(uint4*)(smem + 128 * TST + n * TST + cm * 16);
        size_t g = (size_t)(col0 + n) * NN + row0 + cm * 8;
        *(uint4*)(ThiOut + g) = vh;
        *(uint4*)(TloOut + g) = vl;
    }
}

// ======================= fused softmax + P@Wh GEMM ========================
// 640 threads: warps 0-15 = MMA consumers (M=64 x N=256 tile),
// warps 16-19 = p-producers. K=8192 in 128 chunks of 64.
// A handoff via named barriers FULL(1+s)/EMPTY(4+s), 3 slots. No per-chunk
// __syncthreads. B ring (3 slots) owned by consumers; adj ring by producers.
static constexpr int FB_STG    = 256 * 144;                  // 36864
static constexpr int F_OFF_ADJ = 3 * FB_STG;                 // 110592
static constexpr int F_ADJ_STG = 64 * 272;                   // 17408
static constexpr int F_OFF_A   = F_OFF_ADJ + 3 * F_ADJ_STG;  // 162816
static constexpr int F_A_STG   = 64 * 144;                   // 9216
static constexpr int F_OFF_RS  = F_OFF_A + 3 * F_A_STG;      // 190464
static constexpr int SMEM2_SZ  = F_OFF_RS + 512;             // 190976

__global__ void __launch_bounds__(640, 1) fused_gemm2(
    const int* __restrict__ adj, float* __restrict__ out)
{
    extern __shared__ char smem[];
    const uint32_t sb = smem_u32(smem);
    const int tid  = threadIdx.x;
    const int warp = tid >> 5;
    const int lane = tid & 31;
    const int row0 = blockIdx.x * 64;
    float* rs_part = (float*)(smem + F_OFF_RS);   // [64][2]

    if (warp < 16) {
        // ================= CONSUMER: pure GEMM =================
        const int wm = warp & 1;          // 2 row-groups of 32
        const int wn = warp >> 1;         // 8 col-groups of 32
        const int a_row = lane & 15;
        const int a_kb  = (lane >> 4) * 16;
        const int b_row = ((lane >> 4) << 3) + (lane & 7);
        const int b_kb  = ((lane >> 3) & 1) * 16;

        auto load_B = [&](int slot, int c) {
            if (c < 128) {
                const uint32_t bb = sb + slot * FB_STG;
                const int k0 = c * 64;
                #pragma unroll
                for (int it = 0; it < 4; it++) {
                    int idx = tid + it * 512;        // 0..2047
                    int n = idx >> 3, c8 = idx & 7;
                    cp_async16(bb + n * 144 + c8 * 16,
                               g_WhThi + (size_t)n * NN + k0 + c8 * 8);
                }
            }
            cp_commit();
        };

        float acc[2][4][4];
        #pragma unroll
        for (int i = 0; i < 2; i++)
            #pragma unroll
            for (int j = 0; j < 4; j++)
                #pragma unroll
                for (int q = 0; q < 4; q++) acc[i][j][q] = 0.0f;

        load_B(0, 0); load_B(1, 1); load_B(2, 2);

        int bS = 0;
        for (int c = 0; c < 128; c++) {
            cp_wait<2>();                 // B(c) resident
            bar_sync640(1 + bS);          // A[c] full

            const uint32_t bbase = sb + bS * FB_STG;
            const uint32_t abase = sb + F_OFF_A + bS * F_A_STG;
            #pragma unroll
            for (int ks = 0; ks < 4; ks++) {
                const int kb = ks * 32;
                uint32_t af[2][4], bh[8];
                #pragma unroll
                for (int mt = 0; mt < 2; mt++) {
                    uint32_t ra = abase + (wm * 32 + mt * 16 + a_row) * 144 + kb + a_kb;
                    ldm_x4(ra, af[mt][0], af[mt][1], af[mt][2], af[mt][3]);
                }
                #pragma unroll
                for (int nb = 0; nb < 2; nb++) {
                    uint32_t rb = bbase + (wn * 32 + nb * 16 + b_row) * 144 + kb + b_kb;
                    ldm_x4(rb, bh[4*nb], bh[4*nb+1], bh[4*nb+2], bh[4*nb+3]);
                }
                #pragma unroll
                for (int mt = 0; mt < 2; mt++)
                    #pragma unroll
                    for (int nt = 0; nt < 4; nt++)
                        mma_fp16(acc[mt][nt], af[mt], bh + 2*nt);
            }

            bar_arrive640(4 + bS);        // A[c] consumed
            load_B(bS, c + 3);            // refill freed B slot
            bS = bS == 2 ? 0 : bS + 1;
        }

        __syncthreads();                  // rowsum parts ready

        #pragma unroll
        for (int mt = 0; mt < 2; mt++) {
            int rAl = wm * 32 + mt * 16 + (lane >> 2);
            int rBl = rAl + 8;
            float invA = 1.0f / (rs_part[rAl * 2] + rs_part[rAl * 2 + 1]);
            float invB = 1.0f / (rs_part[rBl * 2] + rs_part[rBl * 2 + 1]);
            #pragma unroll
            for (int nt = 0; nt < 4; nt++) {
                int cc = wn * 32 + nt * 8 + (lane & 3) * 2;
                float v0 = acc[mt][nt][0] * invA;
                float v1 = acc[mt][nt][1] * invA;
                float v2 = acc[mt][nt][2] * invB;
                float v3 = acc[mt][nt][3] * invB;
                float2 oA = { v0 > 0.f ? v0 : expm1f(v0), v1 > 0.f ? v1 : expm1f(v1) };
                float2 oB = { v2 > 0.f ? v2 : expm1f(v2), v3 > 0.f ? v3 : expm1f(v3) };
                *(float2*)(out + (size_t)(row0 + rAl) * FD + cc) = oA;
                *(float2*)(out + (size_t)(row0 + rBl) * FD + cc) = oB;
            }
        }
    } else {
        // ================= PRODUCER: adj -> p =================
        const int pid  = tid - 512;       // 0..127
        const int r    = pid >> 1;        // row 0..63
        const int half = pid & 1;         // k-half: cols half*32..+31

        auto load_adj = [&](int slot, int c) {
            if (c < 128) {
                const uint32_t ab = sb + F_OFF_ADJ + slot * F_ADJ_STG;
                #pragma unroll
                for (int i = 0; i < 8; i++) {
                    int idx = pid * 8 + i;           // 0..1023
                    int r2 = idx >> 4, cc = idx & 15;
                    cp_async16(ab + r2 * 272 + cc * 16,
                               adj + (size_t)(row0 + r2) * NN + c * 64 + cc * 4);
                }
            }
            cp_commit();
        };

        const float f2max = fdec(g_f2max_bits);
        const float f1r = g_f1[row0 + r];
        float t0 = f1r + f2max;
        const float Cr = t0 > 0.f ? t0 : ALPHA_S * t0;
        float psum = 0.f;

        load_adj(0, 0); load_adj(1, 1); load_adj(2, 2);

        int aS = 0;
        for (int c = 0; c < 128; c++) {
            if (c >= 3) bar_sync640(4 + aS);   // A slot free
            cp_wait<2>();                       // adj(c) resident

            const char* ab = smem + F_OFF_ADJ + aS * F_ADJ_STG + r * 272 + half * 128;
            char* dst = smem + F_OFF_A + aS * F_A_STG + r * 144 + half * 64;
            const float* f2p = g_f2 + c * 64 + half * 32;
            #pragma unroll
            for (int j = 0; j < 8; j++) {
                int4 av = ((const int4*)ab)[j];
                float4 f2v = *(const float4*)(f2p + j * 4);
                float a0 = f1r + f2v.x; a0 = a0 > 0.f ? a0 : ALPHA_S * a0;
                float a1 = f1r + f2v.y; a1 = a1 > 0.f ? a1 : ALPHA_S * a1;
                float a2 = f1r + f2v.z; a2 = a2 > 0.f ? a2 : ALPHA_S * a2;
                float a3 = f1r + f2v.w; a3 = a3 > 0.f ? a3 : ALPHA_S * a3;
                float p0 = av.x > 0 ? __expf(a0 - Cr) : 0.f;
                float p1 = av.y > 0 ? __expf(a1 - Cr) : 0.f;
                float p2 = av.z > 0 ? __expf(a2 - Cr) : 0.f;
                float p3 = av.w > 0 ? __expf(a3 - Cr) : 0.f;
                psum += (p0 + p1) + (p2 + p3);
                __half2 h01 = __floats2half2_rn(p0, p1);
                __half2 h23 = __floats2half2_rn(p2, p3);
                uint2 w; w.x = *(uint32_t*)&h01; w.y = *(uint32_t*)&h23;
                *(uint2*)(dst + j * 8) = w;
            }

            bar_arrive640(1 + aS);             // A[c] full
            load_adj(aS, c + 3);               // refill freed adj slot
            aS = aS == 2 ? 0 : aS + 1;
        }

        rs_part[r * 2 + half] = psum;
        __syncthreads();
    }
}

// ---------------- input conversion ----------------
__global__ void convert_kernel(const float* __restrict__ h, const float* __restrict__ W)
{
    if (blockIdx.x == 0 && threadIdx.x == 0) g_f2max_bits = 0u;
    int t = blockIdx.x * 256 + threadIdx.x;
    if (blockIdx.x < NN) {
        float v = h[t];
        __nv_bfloat16 hb = __float2bfloat16(v);
        g_hhi[t] = hb;
        g_hlo[t] = __float2bfloat16(v - __bfloat162float(hb));
    } else {
        int idx = t - NN * 256;
        int o = idx >> 8, i = idx & 255;
        float v = W[i * FD + o];
        __nv_bfloat16 hb = __float2bfloat16(v);
        g_WThi[idx] = hb;
        g_WTlo[idx] = __float2bfloat16(v - __bfloat162float(hb));
    }
}

// ---------------- f1/f2 from WhT splits + global f2 max ----------------
__global__ void f1f2_kernel(const float* __restrict__ a)
{
    __shared__ float red[256];
    int tid = threadIdx.x;
    int m = blockIdx.x * 256 + tid;
    float s1 = 0.0f, s2 = 0.0f;
    #pragma unroll 4
    for (int n = 0; n < FD; n++) {
        float v = __half2float(g_WhThi[(size_t)n * NN + m]) +
                  __half2float(g_WhTlo[(size_t)n * NN + m]);
        s1 = fmaf(v, __ldg(a + n),      s1);
        s2 = fmaf(v, __ldg(a + FD + n), s2);
    }
    g_f1[m] = s1;
    g_f2[m] = s2;

    red[tid] = s2; __syncthreads();
    #pragma unroll
    for (int s = 128; s > 0; s >>= 1) {
        if (tid < s) red[tid] = fmaxf(red[tid], red[tid + s]);
        __syncthreads();
    }
    if (tid == 0) atomicMax(&g_f2max_bits, fkey(red[0]));
}

// ---------------- launch ----------------
extern "C" void kernel_launch(void* const* d_in, const int* in_sizes, int n_in,
                              void* d_out, int out_size)
{
    const float* h   = (const float*)d_in[0];
    const int*   adj = (const int*)  d_in[1];
    const float* W   = (const float*)d_in[3];
    const float* a   = (const float*)d_in[4];
    float* out = (float*)d_out;

    __nv_bfloat16 *phhi, *phlo, *pWThi, *pWTlo;
    __half *pWhThi, *pWhTlo;
    cudaGetSymbolAddress((void**)&phhi,   g_hhi);
    cudaGetSymbolAddress((void**)&phlo,   g_hlo);
    cudaGetSymbolAddress((void**)&pWThi,  g_WThi);
    cudaGetSymbolAddress((void**)&pWTlo,  g_WTlo);
    cudaGetSymbolAddress((void**)&pWhThi, g_WhThi);
    cudaGetSymbolAddress((void**)&pWhTlo, g_WhTlo);

    cudaFuncSetAttribute(mma_gemm1<8>, cudaFuncAttributeMaxDynamicSharedMemorySize, SMEM1_SZ);
    cudaFuncSetAttribute(fused_gemm2,  cudaFuncAttributeMaxDynamicSharedMemorySize, SMEM2_SZ);

    // 1) bf16 hi/lo splits of h and W^T (+ f2max init)
    convert_kernel<<<NN + FD, 256>>>(h, W);

    // 2) Wh = h@W (bf16 3-pass); epilogue writes WhT fp16 hi/lo
    {
        dim3 grid(NN / 128, FD / 128);
        mma_gemm1<8><<<grid, 256, SMEM1_SZ>>>(
            phhi, phlo, pWThi, pWTlo, pWhThi, pWhTlo);
    }

    // 3) f1/f2 (full precision hi+lo) + global f2 max
    f1f2_kernel<<<NN / 256, 256>>>(a);

    // 4) warp-specialized fused masked-softmax + (P @ Wh)/rowsum + ELU
    fused_gemm2<<<NN / 64, 640, SMEM2_SZ>>>(adj, out);
}

// round 10
// speedup vs baseline: 1.1495x; 1.1244x over previous
#include <cuda_runtime.h>
#include <cuda_bf16.h>
#include <cuda_fp16.h>
#include <cstdint>
#include <math.h>

#define NN 8192
#define FD 256
#define ALPHA_S 0.2f

// ---------------- device global scratch ----------------
__device__ __nv_bfloat16 g_hhi[NN * FD];
__device__ __nv_bfloat16 g_hlo[NN * FD];
__device__ __nv_bfloat16 g_WThi[FD * FD];
__device__ __nv_bfloat16 g_WTlo[FD * FD];
__device__ __half g_WhThi[FD * NN];   // Wh^T [n][k] fp16 hi/lo
__device__ __half g_WhTlo[FD * NN];
__device__ float g_f1[NN];
__device__ float4 g_tab[NN];          // {f2, exp(f2), exp(a*f2), 0}
__device__ unsigned int g_f2max_bits;

__device__ __forceinline__ unsigned int fkey(float f) {
    unsigned int b = __float_as_uint(f);
    return (b & 0x80000000u) ? ~b : (b | 0x80000000u);
}
__device__ __forceinline__ float fdec(unsigned int k) {
    unsigned int b = (k & 0x80000000u) ? (k & 0x7fffffffu) : ~k;
    return __uint_as_float(b);
}

// ---------------- PTX helpers ----------------
__device__ __forceinline__ uint32_t smem_u32(const void* p) {
    uint32_t a;
    asm("{ .reg .u64 t; cvta.to.shared.u64 t, %1; cvt.u32.u64 %0, t; }"
        : "=r"(a) : "l"(p));
    return a;
}
__device__ __forceinline__ void cp_async16(uint32_t dst, const void* src) {
    asm volatile("cp.async.cg.shared.global [%0], [%1], 16;"
                 :: "r"(dst), "l"(src) : "memory");
}
__device__ __forceinline__ void cp_commit() {
    asm volatile("cp.async.commit_group;" ::: "memory");
}
template<int N>
__device__ __forceinline__ void cp_wait() {
    asm volatile("cp.async.wait_group %0;" :: "n"(N) : "memory");
}
__device__ __forceinline__ void ldm_x4(uint32_t addr, uint32_t& r0, uint32_t& r1,
                                       uint32_t& r2, uint32_t& r3) {
    asm volatile("ldmatrix.sync.aligned.m8n8.x4.shared.b16 {%0,%1,%2,%3}, [%4];"
                 : "=r"(r0), "=r"(r1), "=r"(r2), "=r"(r3) : "r"(addr));
}
__device__ __forceinline__ void mma_bf16(float* c, const uint32_t* a, const uint32_t* b) {
    asm volatile(
        "mma.sync.aligned.m16n8k16.row.col.f32.bf16.bf16.f32 "
        "{%0,%1,%2,%3}, {%4,%5,%6,%7}, {%8,%9}, {%0,%1,%2,%3};"
        : "+f"(c[0]), "+f"(c[1]), "+f"(c[2]), "+f"(c[3])
        : "r"(a[0]), "r"(a[1]), "r"(a[2]), "r"(a[3]), "r"(b[0]), "r"(b[1]));
}
__device__ __forceinline__ void mma_fp16(float* c, const uint32_t* a, const uint32_t* b) {
    asm volatile(
        "mma.sync.aligned.m16n8k16.row.col.f32.f16.f16.f32 "
        "{%0,%1,%2,%3}, {%4,%5,%6,%7}, {%8,%9}, {%0,%1,%2,%3};"
        : "+f"(c[0]), "+f"(c[1]), "+f"(c[2]), "+f"(c[3])
        : "r"(a[0]), "r"(a[1]), "r"(a[2]), "r"(a[3]), "r"(b[0]), "r"(b[1]));
}

// ======================= GEMM1: Wh = h @ W (bf16 3-pass) ====
static constexpr int ROWB    = 80;
static constexpr int TILE_B  = 128 * ROWB;
static constexpr int STAGE_B = 4 * TILE_B;
static constexpr int SMEM1_SZ = 2 * STAGE_B;      // 81920

template<int KCHUNKS>
__global__ void __launch_bounds__(256, 1) mma_gemm1(
    const __nv_bfloat16* __restrict__ Ahi, const __nv_bfloat16* __restrict__ Alo,
    const __nv_bfloat16* __restrict__ Bhi, const __nv_bfloat16* __restrict__ Blo,
    __half* __restrict__ ThiOut, __half* __restrict__ TloOut)
{
    constexpr int K = KCHUNKS * 32;
    extern __shared__ char smem[];
    const uint32_t sb = smem_u32(smem);

    const int tid  = threadIdx.x;
    const int warp = tid >> 5;
    const int lane = tid & 31;
    const int wm   = warp & 3;
    const int wn   = warp >> 2;
    const int row0 = blockIdx.x * 128;
    const int col0 = blockIdx.y * 128;

    const int a_row = lane & 15;
    const int a_kb  = (lane >> 4) * 16;
    const int b_row = ((lane >> 4) << 3) + (lane & 7);
    const int b_kb  = ((lane >> 3) & 1) * 16;
    const int lrow = tid >> 2;
    const int lch  = tid & 3;

    float acc[2][8][4];
    #pragma unroll
    for (int i = 0; i < 2; i++)
        #pragma unroll
        for (int j = 0; j < 8; j++)
            #pragma unroll
            for (int q = 0; q < 4; q++) acc[i][j][q] = 0.0f;

    auto load_stage = [&](int s, int kc) {
        const uint32_t base = sb + s * STAGE_B;
        const int k0 = kc * 32;
        #pragma unroll
        for (int it = 0; it < 2; it++) {
            int r = lrow + it * 64;
            uint32_t doff = r * ROWB + lch * 16;
            size_t ga = (size_t)(row0 + r) * K + k0 + lch * 8;
            size_t gb = (size_t)(col0 + r) * K + k0 + lch * 8;
            cp_async16(base + 0 * TILE_B + doff, Ahi + ga);
            cp_async16(base + 1 * TILE_B + doff, Alo + ga);
            cp_async16(base + 2 * TILE_B + doff, Bhi + gb);
            cp_async16(base + 3 * TILE_B + doff, Blo + gb);
        }
        cp_commit();
    };

    load_stage(0, 0);

    for (int c = 0; c < KCHUNKS; c++) {
        const int s = c & 1;
        if (c + 1 < KCHUNKS) { load_stage(s ^ 1, c + 1); cp_wait<1>(); }
        else                 { cp_wait<0>(); }
        __syncthreads();

        const uint32_t base = sb + s * STAGE_B;
        #pragma unroll
        for (int ks = 0; ks < 2; ks++) {
            const int kb = ks * 32;
            uint32_t ah[2][4], al[2][4], bh[16], bl[16];
            #pragma unroll
            for (int mt = 0; mt < 2; mt++) {
                uint32_t ra = (wm * 32 + mt * 16 + a_row) * ROWB + kb + a_kb;
                ldm_x4(base + 0 * TILE_B + ra, ah[mt][0], ah[mt][1], ah[mt][2], ah[mt][3]);
                ldm_x4(base + 1 * TILE_B + ra, al[mt][0], al[mt][1], al[mt][2], al[mt][3]);
            }
            #pragma unroll
            for (int nb = 0; nb < 4; nb++) {
                uint32_t rb = (wn * 64 + nb * 16 + b_row) * ROWB + kb + b_kb;
                ldm_x4(base + 2 * TILE_B + rb, bh[4*nb], bh[4*nb+1], bh[4*nb+2], bh[4*nb+3]);
                ldm_x4(base + 3 * TILE_B + rb, bl[4*nb], bl[4*nb+1], bl[4*nb+2], bl[4*nb+3]);
            }
            #pragma unroll
            for (int mt = 0; mt < 2; mt++)
                #pragma unroll
                for (int nt = 0; nt < 8; nt++) {
                    mma_bf16(acc[mt][nt], ah[mt], bh + 2*nt);
                    mma_bf16(acc[mt][nt], ah[mt], bl + 2*nt);
                    mma_bf16(acc[mt][nt], al[mt], bh + 2*nt);
                }
        }
        __syncthreads();
    }

    // stage C^T fp16 hi/lo through smem, then coalesced store to [n][m]
    constexpr int TST = 272;
    __half* shT = (__half*)smem;
    __half* slT = (__half*)(smem + 128 * TST);
    #pragma unroll
    for (int mt = 0; mt < 2; mt++) {
        #pragma unroll
        for (int nt = 0; nt < 8; nt++) {
            int ml = wm * 32 + mt * 16 + (lane >> 2);
            int nl = wn * 64 + nt * 8 + (lane & 3) * 2;
            #pragma unroll
            for (int q = 0; q < 4; q++) {
                int m = ml + (q >> 1) * 8;
                int n = nl + (q & 1);
                float v = acc[mt][nt][q];
                __half hb = __float2half_rn(v);
                __half lb = __float2half_rn(v - __half2float(hb));
                shT[n * 136 + m] = hb;
                slT[n * 136 + m] = lb;
            }
        }
    }
    __syncthreads();
    #pragma unroll
    for (int it = 0; it < 8; it++) {
        int idx = tid + it * 256;
        int n = idx >> 4, cm = idx & 15;
        uint4 vh = *(uint4*)(smem + n * TST + cm * 16);
        uint4 vl = *(uint4*)(smem + 128 * TST + n * TST + cm * 16);
        size_t g = (size_t)(col0 + n) * NN + row0 + cm * 8;
        *(uint4*)(ThiOut + g) = vh;
        *(uint4*)(TloOut + g) = vl;
    }
}

// ======================= fused softmax + P@Wh GEMM ========================
// 512 threads (16 warps: 4 wm x 4 wn), tile M=64 x N=256, 128 chunks of K=64.
// A (p) fragments computed IN REGISTERS per warp via separable exp (no MUFU,
// no A smem, no handoff barrier). One sync/chunk guards B/adj/tab rings only.
static constexpr int FB_STG    = 256 * 144;                  // 36864
static constexpr int F_OFF_ADJ = 3 * FB_STG;                 // 110592
static constexpr int F_ADJ_STG = 64 * 288;                   // 18432 (288B rows: LDS.64 conflict-free)
static constexpr int F_OFF_TAB = F_OFF_ADJ + 3 * F_ADJ_STG;  // 165888
static constexpr int F_TAB_STG = 64 * 16;                    // 1024
static constexpr int F_OFF_RS  = F_OFF_TAB + 3 * F_TAB_STG;  // 168960
static constexpr int SMEM2_SZ  = F_OFF_RS + 256;             // 169216

__device__ __forceinline__ float pval(int av, const float4& t, float f1,
                                      float cp, float cn) {
    float s = f1 + t.x;
    float m = s > 0.f ? cp * t.y : cn * t.z;
    return av > 0 ? m : 0.f;
}
__device__ __forceinline__ uint32_t pack2(float a, float b) {
    __half2 h = __floats2half2_rn(a, b);
    return *(uint32_t*)&h;
}

__global__ void __launch_bounds__(512, 1) fused_gemm2(
    const int* __restrict__ adj, float* __restrict__ out)
{
    extern __shared__ char smem[];
    const uint32_t sb = smem_u32(smem);
    const int tid  = threadIdx.x;
    const int warp = tid >> 5;
    const int lane = tid & 31;
    const int wm   = warp & 3;            // m16 tile: rows wm*16
    const int wn   = warp >> 2;           // n64 tile: cols wn*64
    const int lq   = lane & 3;
    const int row0 = blockIdx.x * 64;
    const int r0l  = wm * 16 + (lane >> 2);   // this lane's frag row (and +8)

    const int b_row = ((lane >> 4) << 3) + (lane & 7);
    const int b_kb  = ((lane >> 3) & 1) * 16;

    auto load_B = [&](int c) {
        if (c < 128) {
            const uint32_t bb = sb + (c % 3) * FB_STG;
            const int k0 = c * 64;
            #pragma unroll
            for (int it = 0; it < 4; it++) {
                int idx = tid + it * 512;
                int n = idx >> 3, c8 = idx & 7;
                cp_async16(bb + n * 144 + c8 * 16,
                           g_WhThi + (size_t)n * NN + k0 + c8 * 8);
            }
        }
    };
    auto load_AT = [&](int c) {
        if (c < 128) {
            const uint32_t ab = sb + F_OFF_ADJ + (c % 3) * F_ADJ_STG;
            #pragma unroll
            for (int it = 0; it < 2; it++) {
                int idx = tid + it * 512;
                int r = idx >> 4, q = idx & 15;
                cp_async16(ab + r * 288 + q * 16,
                           adj + (size_t)(row0 + r) * NN + c * 64 + q * 4);
            }
            if (tid < 64) {
                const uint32_t tb = sb + F_OFF_TAB + (c % 3) * F_TAB_STG;
                cp_async16(tb + tid * 16, g_tab + c * 64 + tid);
            }
        }
    };

    // per-row constants (any per-row shift cancels in softmax)
    const float f2max = fdec(g_f2max_bits);
    const float f10 = g_f1[row0 + r0l];
    const float f11 = g_f1[row0 + r0l + 8];
    float tt;
    tt = f10 + f2max; const float Cr0 = tt > 0.f ? tt : ALPHA_S * tt;
    tt = f11 + f2max; const float Cr1 = tt > 0.f ? tt : ALPHA_S * tt;
    const float c1p0 = __expf(f10 - Cr0), c1n0 = __expf(ALPHA_S * f10 - Cr0);
    const float c1p1 = __expf(f11 - Cr1), c1n1 = __expf(ALPHA_S * f11 - Cr1);
    float psum0 = 0.f, psum1 = 0.f;

    uint32_t afrag[4][4];
    float acc[8][4];
    #pragma unroll
    for (int j = 0; j < 8; j++)
        #pragma unroll
        for (int q = 0; q < 4; q++) acc[j][q] = 0.0f;

    auto computeA = [&](int c) {
        const char* ab = smem + F_OFF_ADJ + (c % 3) * F_ADJ_STG + r0l * 288;
        const char* tb = smem + F_OFF_TAB + (c % 3) * F_TAB_STG;
        #pragma unroll
        for (int ks = 0; ks < 4; ks++) {
            const int colb = ks * 16 + 2 * lq;
            float4 t0 = *(const float4*)(tb + (colb    ) * 16);
            float4 t1 = *(const float4*)(tb + (colb + 1) * 16);
            float4 t8 = *(const float4*)(tb + (colb + 8) * 16);
            float4 t9 = *(const float4*)(tb + (colb + 9) * 16);
            const char* ar = ab + ks * 64 + lq * 8;
            int2 a0  = *(const int2*)(ar);
            int2 a0b = *(const int2*)(ar + 32);
            int2 a1  = *(const int2*)(ar + 8 * 288);
            int2 a1b = *(const int2*)(ar + 8 * 288 + 32);
            float p00 = pval(a0.x,  t0, f10, c1p0, c1n0);
            float p01 = pval(a0.y,  t1, f10, c1p0, c1n0);
            float p08 = pval(a0b.x, t8, f10, c1p0, c1n0);
            float p09 = pval(a0b.y, t9, f10, c1p0, c1n0);
            float p10 = pval(a1.x,  t0, f11, c1p1, c1n1);
            float p11 = pval(a1.y,  t1, f11, c1p1, c1n1);
            float p18 = pval(a1b.x, t8, f11, c1p1, c1n1);
            float p19 = pval(a1b.y, t9, f11, c1p1, c1n1);
            afrag[ks][0] = pack2(p00, p01);
            afrag[ks][1] = pack2(p10, p11);
            afrag[ks][2] = pack2(p08, p09);
            afrag[ks][3] = pack2(p18, p19);
            if (wn == 0) {
                psum0 += (p00 + p01) + (p08 + p09);
                psum1 += (p10 + p11) + (p18 + p19);
            }
        }
    };

    // prologue: Gp1={B0, AT0, AT1}, Gp2={B1, AT2}
    load_B(0); load_AT(0); load_AT(1); cp_commit();
    load_B(1); load_AT(2);            cp_commit();
    cp_wait<1>();                 // Gp1 done
    __syncthreads();
    computeA(0);

    for (int c = 0; c < 128; c++) {
        cp_wait<1>();             // {B(c), adj(c+1), tab(c+1)} done
        __syncthreads();          // ring slots safe to refill / read
        load_B(c + 2); load_AT(c + 3); cp_commit();

        const uint32_t bb = sb + (c % 3) * FB_STG;
        #pragma unroll
        for (int ks = 0; ks < 4; ks++) {
            uint32_t bh[16];
            #pragma unroll
            for (int nb = 0; nb < 4; nb++) {
                uint32_t rb = bb + (wn * 64 + nb * 16 + b_row) * 144 + ks * 32 + b_kb;
                ldm_x4(rb, bh[4*nb], bh[4*nb+1], bh[4*nb+2], bh[4*nb+3]);
            }
            #pragma unroll
            for (int nt = 0; nt < 8; nt++)
                mma_fp16(acc[nt], afrag[ks], bh + 2*nt);
        }

        if (c + 1 < 128) computeA(c + 1);   // in the MMA shadow, no barrier
    }

    // ---- rowsums: wn==0 warps hold full per-row sums after quad reduce ----
    float* rs = (float*)(smem + F_OFF_RS);
    if (wn == 0) {
        psum0 += __shfl_xor_sync(0xffffffffu, psum0, 1);
        psum0 += __shfl_xor_sync(0xffffffffu, psum0, 2);
        psum1 += __shfl_xor_sync(0xffffffffu, psum1, 1);
        psum1 += __shfl_xor_sync(0xffffffffu, psum1, 2);
        if (lq == 0) {
            rs[r0l]     = psum0;
            rs[r0l + 8] = psum1;
        }
    }
    __syncthreads();

    // ---- epilogue: out = elu(acc / rowsum) ----
    const float invA = 1.0f / rs[r0l];
    const float invB = 1.0f / rs[r0l + 8];
    #pragma unroll
    for (int nt = 0; nt < 8; nt++) {
        int cc = wn * 64 + nt * 8 + lq * 2;
        float v0 = acc[nt][0] * invA;
        float v1 = acc[nt][1] * invA;
        float v2 = acc[nt][2] * invB;
        float v3 = acc[nt][3] * invB;
        float2 oA = { v0 > 0.f ? v0 : expm1f(v0), v1 > 0.f ? v1 : expm1f(v1) };
        float2 oB = { v2 > 0.f ? v2 : expm1f(v2), v3 > 0.f ? v3 : expm1f(v3) };
        *(float2*)(out + (size_t)(row0 + r0l) * FD + cc) = oA;
        *(float2*)(out + (size_t)(row0 + r0l + 8) * FD + cc) = oB;
    }
}

// ---------------- input conversion ----------------
__global__ void convert_kernel(const float* __restrict__ h, const float* __restrict__ W)
{
    if (blockIdx.x == 0 && threadIdx.x == 0) g_f2max_bits = 0u;
    int t = blockIdx.x * 256 + threadIdx.x;
    if (blockIdx.x < NN) {
        float v = h[t];
        __nv_bfloat16 hb = __float2bfloat16(v);
        g_hhi[t] = hb;
        g_hlo[t] = __float2bfloat16(v - __bfloat162float(hb));
    } else {
        int idx = t - NN * 256;
        int o = idx >> 8, i = idx & 255;
        float v = W[i * FD + o];
        __nv_bfloat16 hb = __float2bfloat16(v);
        g_WThi[idx] = hb;
        g_WTlo[idx] = __float2bfloat16(v - __bfloat162float(hb));
    }
}

// ------- f1/f2 from WhT splits + exp tables + global f2 max -------
__global__ void f1f2_kernel(const float* __restrict__ a)
{
    __shared__ float red[256];
    int tid = threadIdx.x;
    int m = blockIdx.x * 256 + tid;
    float s1 = 0.0f, s2 = 0.0f;
    #pragma unroll 4
    for (int n = 0; n < FD; n++) {
        float v = __half2float(g_WhThi[(size_t)n * NN + m]) +
                  __half2float(g_WhTlo[(size_t)n * NN + m]);
        s1 = fmaf(v, __ldg(a + n),      s1);
        s2 = fmaf(v, __ldg(a + FD + n), s2);
    }
    g_f1[m] = s1;
    float s2c = fminf(s2, 60.f);
    g_tab[m] = make_float4(s2, __expf(s2c), __expf(ALPHA_S * s2c), 0.f);

    red[tid] = s2; __syncthreads();
    #pragma unroll
    for (int s = 128; s > 0; s >>= 1) {
        if (tid < s) red[tid] = fmaxf(red[tid], red[tid + s]);
        __syncthreads();
    }
    if (tid == 0) atomicMax(&g_f2max_bits, fkey(red[0]));
}

// ---------------- launch ----------------
extern "C" void kernel_launch(void* const* d_in, const int* in_sizes, int n_in,
                              void* d_out, int out_size)
{
    const float* h   = (const float*)d_in[0];
    const int*   adj = (const int*)  d_in[1];
    const float* W   = (const float*)d_in[3];
    const float* a   = (const float*)d_in[4];
    float* out = (float*)d_out;

    __nv_bfloat16 *phhi, *phlo, *pWThi, *pWTlo;
    __half *pWhThi, *pWhTlo;
    cudaGetSymbolAddress((void**)&phhi,   g_hhi);
    cudaGetSymbolAddress((void**)&phlo,   g_hlo);
    cudaGetSymbolAddress((void**)&pWThi,  g_WThi);
    cudaGetSymbolAddress((void**)&pWTlo,  g_WTlo);
    cudaGetSymbolAddress((void**)&pWhThi, g_WhThi);
    cudaGetSymbolAddress((void**)&pWhTlo, g_WhTlo);

    cudaFuncSetAttribute(mma_gemm1<8>, cudaFuncAttributeMaxDynamicSharedMemorySize, SMEM1_SZ);
    cudaFuncSetAttribute(fused_gemm2,  cudaFuncAttributeMaxDynamicSharedMemorySize, SMEM2_SZ);

    // 1) bf16 hi/lo splits of h and W^T (+ f2max init)
    convert_kernel<<<NN + FD, 256>>>(h, W);

    // 2) Wh = h@W (bf16 3-pass); epilogue writes WhT fp16 hi/lo
    {
        dim3 grid(NN / 128, FD / 128);
        mma_gemm1<8><<<grid, 256, SMEM1_SZ>>>(
            phhi, phlo, pWThi, pWTlo, pWhThi, pWhTlo);
    }

    // 3) f1 + exp tables (full precision hi+lo) + global f2 max
    f1f2_kernel<<<NN / 256, 256>>>(a);

    // 4) fused masked-softmax + (P @ Wh)/rowsum + ELU, A-in-registers
    fused_gemm2<<<NN / 64, 512, SMEM2_SZ>>>(adj, out);
}